// round 5
// baseline (speedup 1.0000x reference)
#include <cuda_runtime.h>

// Grouped shifted conv1d:
//   t = roll(x, +1, axis=3); patches = unfold(t, k=3, pad=1) along last axis
//   y[o,k,n,m] = sum_{i,j} patches[o*64+i, n, j, m] * W[i,k,j]
//   out = roll(y, +1, axis=2)  (H roll folded into store index)
//
// Grid: (56 rows, 2 groups). Block: 896 threads = 56 m x 4 k-quads x 4 i-quarters.
// Inner math uses sm_103a packed fma.rn.f32x2 (k packed in pairs).

#define NT 896

__global__ void __launch_bounds__(NT)
shiftconv_kernel(const float* __restrict__ x,
                 const float* __restrict__ W,
                 float* __restrict__ out)
{
    const int n = blockIdx.x;   // input H row 0..55
    const int o = blockIdx.y;   // channel group 0..1

    __shared__ float  xs[64 * 58];   // pre-rolled + zero-padded row slab
    __shared__ float  ws[64 * 48];   // W re-laid-out [i][j][k]
    __shared__ float4 red[3 * 224];  // partials from i-quarters 1..3

    const int tid = threadIdx.x;
    const int m   = tid % 56;
    const int r   = tid / 56;       // 0..15
    const int kq  = r & 3;          // 0..3
    const int iq  = r >> 2;         // 0..3

    // zero the two pad columns (independent smem stores)
    if (tid < 128)
        xs[(tid >> 1) * 58 + (tid & 1) * 57] = 0.0f;

    // --- issue all x LDGs first (biggest latency), MLP=4 ---
    const float* xg  = x + (o * 64) * 3136 + n * 56;
    const int    src = (m + 55) % 56;           // fused +1 circular roll
    const float v0 = xg[(r     ) * 3136 + src];
    const float v1 = xg[(r + 16) * 3136 + src];
    const float v2 = xg[(r + 32) * 3136 + src];
    const float v3 = xg[(r + 48) * 3136 + src];

    // --- W staging overlapped with x loads in flight ---
    // src layout (i,k,j) row-major -> dst [i][j][k]
    #pragma unroll
    for (int s = 0; s < 4; ++s) {
        const int t = tid + s * NT;
        if (t < 64 * 48) {
            const int k = t & 15;
            const int j = (t >> 4) % 3;
            const int i = t / 48;
            ws[t] = W[i * 48 + k * 3 + j];
        }
    }

    xs[(r     ) * 58 + m + 1] = v0;
    xs[(r + 16) * 58 + m + 1] = v1;
    xs[(r + 32) * 58 + m + 1] = v2;
    xs[(r + 48) * 58 + m + 1] = v3;
    __syncthreads();

    // --- compute: thread owns (m, k-quad, i-quarter), 16-iter loop ---
    // k packed in pairs: acc01 covers (kbase, kbase+1), acc23 covers (kbase+2, kbase+3).
    // Two independent chains per packed acc (taps {a,c} vs tap {b}) to cut dep latency.
    const int kbase = kq * 4;
    const float* xsp = xs + iq * 16 * 58 + m;
    const float* wsp = ws + iq * 16 * 48 + kbase;

    unsigned long long accA0 = 0ull, accA1 = 0ull;   // k pair 0-1
    unsigned long long accB0 = 0ull, accB1 = 0ull;   // k pair 2-3

    #pragma unroll
    for (int i = 0; i < 16; ++i) {
        const float a = xsp[i * 58];        // tap j=0
        const float b = xsp[i * 58 + 1];    // tap j=1
        const float c = xsp[i * 58 + 2];    // tap j=2

        const float4 w0 = *reinterpret_cast<const float4*>(wsp + i * 48);
        const float4 w1 = *reinterpret_cast<const float4*>(wsp + i * 48 + 16);
        const float4 w2 = *reinterpret_cast<const float4*>(wsp + i * 48 + 32);

        unsigned long long a2, b2, c2;
        asm("mov.b64 %0, {%1, %1};" : "=l"(a2) : "f"(a));
        asm("mov.b64 %0, {%1, %1};" : "=l"(b2) : "f"(b));
        asm("mov.b64 %0, {%1, %1};" : "=l"(c2) : "f"(c));

        unsigned long long w0lo, w0hi, w1lo, w1hi, w2lo, w2hi;
        asm("mov.b64 %0, {%1, %2};" : "=l"(w0lo) : "f"(w0.x), "f"(w0.y));
        asm("mov.b64 %0, {%1, %2};" : "=l"(w0hi) : "f"(w0.z), "f"(w0.w));
        asm("mov.b64 %0, {%1, %2};" : "=l"(w1lo) : "f"(w1.x), "f"(w1.y));
        asm("mov.b64 %0, {%1, %2};" : "=l"(w1hi) : "f"(w1.z), "f"(w1.w));
        asm("mov.b64 %0, {%1, %2};" : "=l"(w2lo) : "f"(w2.x), "f"(w2.y));
        asm("mov.b64 %0, {%1, %2};" : "=l"(w2hi) : "f"(w2.z), "f"(w2.w));

        asm("fma.rn.f32x2 %0, %1, %2, %0;" : "+l"(accA0) : "l"(a2), "l"(w0lo));
        asm("fma.rn.f32x2 %0, %1, %2, %0;" : "+l"(accA1) : "l"(b2), "l"(w1lo));
        asm("fma.rn.f32x2 %0, %1, %2, %0;" : "+l"(accA0) : "l"(c2), "l"(w2lo));
        asm("fma.rn.f32x2 %0, %1, %2, %0;" : "+l"(accB0) : "l"(a2), "l"(w0hi));
        asm("fma.rn.f32x2 %0, %1, %2, %0;" : "+l"(accB1) : "l"(b2), "l"(w1hi));
        asm("fma.rn.f32x2 %0, %1, %2, %0;" : "+l"(accB0) : "l"(c2), "l"(w2hi));
    }

    // combine split chains, then unpack
    asm("add.rn.f32x2 %0, %0, %1;" : "+l"(accA0) : "l"(accA1));
    asm("add.rn.f32x2 %0, %0, %1;" : "+l"(accB0) : "l"(accB1));

    float acc0, acc1, acc2, acc3;
    asm("mov.b64 {%0, %1}, %2;" : "=f"(acc0), "=f"(acc1) : "l"(accA0));
    asm("mov.b64 {%0, %1}, %2;" : "=f"(acc2), "=f"(acc3) : "l"(accB0));

    // --- 4-way partial reduction through smem ---
    const int part = kq * 56 + m;           // 0..223
    if (iq != 0)
        red[(iq - 1) * 224 + part] = make_float4(acc0, acc1, acc2, acc3);
    __syncthreads();

    if (iq == 0) {
        const float4 p0 = red[part];
        const float4 p1 = red[224 + part];
        const float4 p2 = red[448 + part];
        acc0 += p0.x + p1.x + p2.x;
        acc1 += p0.y + p1.y + p2.y;
        acc2 += p0.z + p1.z + p2.z;
        acc3 += p0.w + p1.w + p2.w;

        // store with the output H-roll folded in: y_out[n+1] = y[n]
        const int n_out = (n + 1) % 56;
        float* og = out + ((o * 16 + kbase) * 56 + n_out) * 56 + m;
        og[0 * 3136] = acc0;
        og[1 * 3136] = acc1;
        og[2 * 3136] = acc2;
        og[3 * 3136] = acc3;
    }
}

extern "C" void kernel_launch(void* const* d_in, const int* in_sizes, int n_in,
                              void* d_out, int out_size)
{
    const float* x = (const float*)d_in[0];   // (1,128,56,56) fp32
    const float* W = (const float*)d_in[1];   // (64,16,3) fp32
    float* out     = (float*)d_out;           // (1,32,56,56) fp32

    dim3 grid(56, 2);
    shiftconv_kernel<<<grid, NT>>>(x, W, out);
}